// round 16
// baseline (speedup 1.0000x reference)
#include <cuda_runtime.h>
#include <cuda_bf16.h>
#include <cuda_fp16.h>
#include <math.h>
#include <cstdint>

#define BATCH   32
#define HEADS   8
#define SEQ     512
#define DMODEL  1024
#define DHEAD   128
#define DCOL    18
#define BHS     (BATCH*HEADS)   // 256
#define BSD     ((size_t)BATCH*SEQ*DMODEL)   // 16777216
#define SCALE   0.08838834764831845f

// ---------------- scratch (static device globals; no allocation) ----------------
__device__ __align__(256) __half        g_xqf[BSD], g_xkf[BSD];          // fp16 inputs
__device__ __align__(256) __half        g_Whf[DMODEL*DMODEL], g_Wvf[DMODEL*DMODEL];
__device__ __align__(256) __half        g_Wof[DMODEL*DMODEL];
__device__ __align__(256) __half        g_fhf[BSD], g_ftf[BSD];          // f_head/f_tail fp16
__device__ __align__(256) float         g_fv [BSD];                      // f_v fp32
__device__ __align__(256) __half        g_atf[BSD];                      // attn fp16
__device__ __align__(256) float         g_adjm[(size_t)HEADS*SEQ*SEQ];
__device__ __align__(256) __half        g_uf [(size_t)BHS*SEQ*SEQ];      // u = exp(l - tm) fp16

// ---------------- small helpers ----------------
__device__ __forceinline__ unsigned packh(float f0, float f1) {    // f0 -> low half
    unsigned d;
    asm("cvt.rn.f16x2.f32 %0, %1, %2;" : "=r"(d) : "f"(f1), "f"(f0));
    return d;
}
__device__ __forceinline__ float2 h2f2(unsigned p) {
    return __half22float2(*reinterpret_cast<__half2*>(&p));
}

__device__ __forceinline__ unsigned smem_u32(const void* p) {
    unsigned a;
    asm("{ .reg .u64 t; cvta.to.shared.u64 t, %1; cvt.u32.u64 %0, t; }" : "=r"(a) : "l"(p));
    return a;
}
__device__ __forceinline__ void cpa16s(unsigned dst, const void* src) {
    asm volatile("cp.async.ca.shared.global [%0], [%1], 16;" :: "r"(dst), "l"(src));
}
__device__ __forceinline__ void cpa_commit() { asm volatile("cp.async.commit_group;"); }
template<int N>
__device__ __forceinline__ void cpa_wait() { asm volatile("cp.async.wait_group %0;" :: "n"(N)); }

__device__ __forceinline__ void ldm4(unsigned& r0, unsigned& r1, unsigned& r2, unsigned& r3,
                                     unsigned addr) {
    asm volatile("ldmatrix.sync.aligned.m8n8.x4.shared.b16 {%0,%1,%2,%3}, [%4];"
                 : "=r"(r0), "=r"(r1), "=r"(r2), "=r"(r3) : "r"(addr));
}

__device__ __forceinline__ void mmah(float* c, unsigned a0, unsigned a1, unsigned a2,
                                     unsigned a3, unsigned b0, unsigned b1) {
    asm volatile(
        "mma.sync.aligned.m16n8k16.row.col.f32.f16.f16.f32 "
        "{%0,%1,%2,%3}, {%4,%5,%6,%7}, {%8,%9}, {%0,%1,%2,%3};\n"
        : "+f"(c[0]), "+f"(c[1]), "+f"(c[2]), "+f"(c[3])
        : "r"(a0), "r"(a1), "r"(a2), "r"(a3), "r"(b0), "r"(b1));
}

// ---------------- conversions (all fp16) ----------------
__global__ void cvt_x(const float* __restrict__ xq, const float* __restrict__ xkv)
{
    const int sel = blockIdx.y;
    const float4* s4 = reinterpret_cast<const float4*>(sel ? xkv : xq);
    uint2* out = reinterpret_cast<uint2*>(sel ? g_xkf : g_xqf);
    const int n4 = (int)(BSD/4);
    for (int i = blockIdx.x * blockDim.x + threadIdx.x; i < n4; i += gridDim.x * blockDim.x) {
        float4 v = s4[i];
        out[i] = make_uint2(packh(v.x, v.y), packh(v.z, v.w));
    }
}

__global__ void cvt_w(const float* __restrict__ wh, const float* __restrict__ wv,
                      const float* __restrict__ wo)
{
    const int sel = blockIdx.y;
    const float4* s4 = reinterpret_cast<const float4*>(sel == 0 ? wh : sel == 1 ? wv : wo);
    uint2* out = reinterpret_cast<uint2*>(sel == 0 ? g_Whf : sel == 1 ? g_Wvf : g_Wof);
    const int n4 = DMODEL*DMODEL/4;
    for (int i = blockIdx.x * blockDim.x + threadIdx.x; i < n4; i += gridDim.x * blockDim.x) {
        float4 v = s4[i];
        out[i] = make_uint2(packh(v.x, v.y), packh(v.z, v.w));
    }
}

// ---------------- adjacency: softmax(col_head @ col_tail^T, diag=0) ----------------
__global__ void adj_kernel(const float* __restrict__ col_head,
                           const float* __restrict__ col_tail)
{
    const int q = blockIdx.x;
    const int h = blockIdx.y;
    const int t = threadIdx.x;                 // 128 threads
    __shared__ float ch[DCOL];
    __shared__ float sred[4];

    if (t < DCOL) ch[t] = col_head[((size_t)h*SEQ + q)*DCOL + t];
    __syncthreads();

    float l[4];
#pragma unroll
    for (int i = 0; i < 4; i++) {
        const int k = t + i*128;
        const float* ct = col_tail + ((size_t)h*SEQ + k)*DCOL;
        float s = 0.f;
#pragma unroll
        for (int c = 0; c < DCOL; c++) s += ch[c]*ct[c];
        l[i] = (k == q) ? 0.f : s;
    }

    float mx = fmaxf(fmaxf(l[0],l[1]), fmaxf(l[2],l[3]));
#pragma unroll
    for (int o = 16; o; o >>= 1) mx = fmaxf(mx, __shfl_xor_sync(0xffffffffu, mx, o));
    if ((t & 31) == 0) sred[t >> 5] = mx;
    __syncthreads();
    mx = fmaxf(fmaxf(sred[0],sred[1]), fmaxf(sred[2],sred[3]));
    __syncthreads();

    float e[4]; float sum = 0.f;
#pragma unroll
    for (int i = 0; i < 4; i++) { e[i] = expf(l[i]-mx); sum += e[i]; }
#pragma unroll
    for (int o = 16; o; o >>= 1) sum += __shfl_xor_sync(0xffffffffu, sum, o);
    if ((t & 31) == 0) sred[t >> 5] = sum;
    __syncthreads();
    sum = sred[0]+sred[1]+sred[2]+sred[3];
    const float inv = 1.f/sum;

    float* dst = g_adjm + ((size_t)h*SEQ + q)*SEQ;
#pragma unroll
    for (int i = 0; i < 4; i++) {
        const int k = t + i*128;
        dst[k] = (1.f - e[i]*inv) * (-10000.f);
    }
}

// ---------------- tile constants ----------------
#define LDK     40                  // padded smem row (16b elems), 80 B
#define TILEB   (128*LDK*2)         // 10240 B (128-row tile)
#define HSTAGE  (2*TILEB)           // attn pass-1 stage: A + B (both 128 rows)
// wide-tile (128x256) GEMM stages:
#define ATILEB  TILEB               // 10240
#define BTILEB  (256*LDK*2)         // 20480
#define STG2    (ATILEB + BTILEB)   // 30720
#define HG2_DSM (3*STG2)            // 92160 (3-stage)

// ---------------- fp16 wide-tile GEMM core (BM=128, BN=256, 8 warps of 64x64) -------
// MODE 0/1/2: projections (A = x_q|x_kv, B = W_head|W_v)
// MODE 3:     out proj    (A = g_atf,    B = W_out) -> Cext fp32
template<int MODE>
__global__ void __launch_bounds__(256, 1)
gemm_wide(const float* __restrict__ biasH, const float* __restrict__ biasV,
          const float* __restrict__ aux, float* __restrict__ Cext, int K)
{
    extern __shared__ char sm[];
    const unsigned sbase = smem_u32(sm);

    const int tid  = threadIdx.x;
    const int lane = tid & 31;
    const int warp = tid >> 5;
    const int wm   = warp >> 2;        // 0..1  (64 rows)
    const int wn   = warp & 3;         // 0..3  (64 cols)
    const int mode = (MODE == 3) ? 3 : blockIdx.z;
    const int m0   = blockIdx.y * 128;
    const int n0   = blockIdx.x * 256;

    const __half* A;
    const __half* B;
    const float* bias;
    if constexpr (MODE == 3) { A = g_atf; B = g_Wof; bias = biasH; }
    else {
        A = (mode == 0) ? g_xqf : g_xkf;
        B = (mode == 2) ? g_Wvf : g_Whf;
        bias = (mode == 2) ? biasV : biasH;
    }

    auto load_stage = [&](int st, int kt) {
        const unsigned sb = sbase + st*STG2;
#pragma unroll
        for (int i = 0; i < 6; i++) {
            const int idx = tid + i*256;       // 0..1535 16B-chunks
            if (idx < 512) {                   // A tile: 128 rows x 4 chunks
                const int r = idx >> 2, c = idx & 3;
                cpa16s(sb + r*80 + c*16, A + (size_t)(m0 + r)*K + kt + c*8);
            } else {                           // B tile: 256 rows x 4 chunks
                const int j = idx - 512;
                const int r = j >> 2, c = j & 3;
                cpa16s(sb + ATILEB + r*80 + c*16, B + (size_t)(n0 + r)*K + kt + c*8);
            }
        }
    };

    float acc[4][8][4];
#pragma unroll
    for (int i = 0; i < 4; i++)
#pragma unroll
        for (int j = 0; j < 8; j++)
#pragma unroll
            for (int f = 0; f < 4; f++) acc[i][j][f] = 0.f;

    const int rowA = (lane & 7) + ((lane >> 3) & 1) * 8;
    const int colA = ((lane >> 4) & 1) * 8;
    const int rowB = (lane & 7) + ((lane >> 4) & 1) * 8;
    const int colB = ((lane >> 3) & 1) * 8;

    const int iters = K >> 5;
    load_stage(0, 0);  cpa_commit();
    load_stage(1, 32); cpa_commit();

    int cur = 0;
    for (int it = 0; it < iters; ++it) {
        if (it + 1 < iters) cpa_wait<1>();
        else                cpa_wait<0>();
        __syncthreads();
        if (it + 2 < iters) {
            load_stage((cur + 2) % 3, (it + 2) << 5);
            cpa_commit();
        }

        const unsigned sb = sbase + cur*STG2;
        const unsigned aA = sb + (wm*64 + rowA)*80 + colA*2;
        const unsigned aB = sb + ATILEB + (wn*64 + rowB)*80 + colB*2;

#pragma unroll
        for (int ks = 0; ks < 2; ks++) {
            const unsigned ko = ks*32;
            unsigned bh[8][2];
#pragma unroll
            for (int g = 0; g < 4; g++) {
                unsigned r0, r1, r2, r3;
                ldm4(r0, r1, r2, r3, aB + g*16*80 + ko);
                bh[2*g][0]=r0; bh[2*g][1]=r1; bh[2*g+1][0]=r2; bh[2*g+1][1]=r3;
            }
#pragma unroll
            for (int mt = 0; mt < 4; mt++) {
                unsigned a[4];
                ldm4(a[0], a[1], a[2], a[3], aA + mt*16*80 + ko);
#pragma unroll
                for (int nt = 0; nt < 8; nt++)
                    mmah(acc[mt][nt], a[0],a[1],a[2],a[3], bh[nt][0], bh[nt][1]);
            }
        }
        cur = (cur == 2) ? 0 : cur + 1;
    }

    const int lr2 = lane >> 2;
    const int lc2 = (lane & 3) << 1;
#pragma unroll
    for (int mt = 0; mt < 4; mt++)
#pragma unroll
        for (int nt = 0; nt < 8; nt++) {
#pragma unroll
            for (int hh = 0; hh < 2; hh++) {
                const int m = m0 + wm*64 + mt*16 + lr2 + hh*8;
                const int n = n0 + wn*64 + nt*8 + lc2;
                float v0 = acc[mt][nt][hh*2+0] + bias[n];
                float v1 = acc[mt][nt][hh*2+1] + bias[n+1];
                if constexpr (MODE == 3) {
                    float2 o; o.x = v0; o.y = v1;
                    *reinterpret_cast<float2*>(&Cext[(size_t)m*DMODEL + n]) = o;
                } else {
                    const int b = m >> 9, q = m & 511, h = n >> 7, dh = n & 127;
                    const size_t idx = (((size_t)((b<<3)|h))*SEQ + q)*DHEAD + dh;
                    if (mode < 2) {
                        v0 *= aux[n]; v1 *= aux[n+1];
                        __half* dst = (mode == 0) ? g_fhf : g_ftf;
                        *reinterpret_cast<unsigned*>(&dst[idx]) = packh(v0, v1);
                    } else {
                        float2 o; o.x = v0; o.y = v1;
                        *reinterpret_cast<float2*>(&g_fv[idx]) = o;
                    }
                }
            }
        }
}

// ---------------- fused scores + softmax + P @ V (unchanged from R15) ----------------
#define FU_TM    49152                 // tm:  [4][128] fp32 (2 KB)
#define FU_TS    (FU_TM + 2048)        // ts:  [4][128]
#define FU_MP    (FU_TM + 4096)        // m_part: [128][4]
#define FU_SP    (FU_TM + 6144)        // s_part: [128][4]
#define FU_FAC   (FU_TM + 8192)        // fac: [4][128]
#define FU_DSM   (FU_TM + 10240)       // 59392

__global__ void __launch_bounds__(256, 2)
attn_fused(float* __restrict__ fr)
{
    extern __shared__ char sm[];
    const unsigned sbase = smem_u32(sm);
    unsigned* pW  = reinterpret_cast<unsigned*>(sm);
    float* tm     = reinterpret_cast<float*>(sm + FU_TM);
    float* ts     = reinterpret_cast<float*>(sm + FU_TS);
    float* m_part = reinterpret_cast<float*>(sm + FU_MP);
    float* s_part = reinterpret_cast<float*>(sm + FU_SP);
    float* fac    = reinterpret_cast<float*>(sm + FU_FAC);

    const int tid  = threadIdx.x;
    const int lane = tid & 31;
    const int warp = tid >> 5;
    const int wm   = warp >> 2, wn = warp & 3;
    const int lr2  = lane >> 2;
    const int lc2  = (lane & 3) << 1;
    const int lc   = lane & 3;
    const int z    = blockIdx.z;
    const int m0   = blockIdx.y * 128;
    const int h    = z & 7;

    const __half* Af = g_fhf + (size_t)z*SEQ*DHEAD;
    const __half* Bf = g_ftf + (size_t)z*SEQ*DHEAD;
    float*  frz = fr   + (size_t)z*SEQ*SEQ;
    __half* ufz = g_uf + (size_t)z*SEQ*SEQ;

    const int rowA = (lane & 7) + ((lane >> 3) & 1) * 8;
    const int colA = ((lane >> 4) & 1) * 8;
    const int rowB = (lane & 7) + ((lane >> 4) & 1) * 8;
    const int colB = ((lane >> 3) & 1) * 8;

    // ================= pass 1: scores -> u fp16, per-tile stats =================
    for (int ntile = 0; ntile < 4; ++ntile) {
        const int n0 = ntile * 128;

        auto load_stage = [&](int st, int kt) {
            const unsigned sb = sbase + st*HSTAGE;
#pragma unroll
            for (int i = 0; i < 4; i++) {
                const int idx  = tid + i*256;
                const int tile = idx >> 9;
                const int r    = (idx >> 2) & 127;
                const int c    = idx & 3;
                const __half* s = tile ? Bf : Af;
                const int rg = (tile ? n0 : m0) + r;
                cpa16s(sb + tile*TILEB + r*(LDK*2) + c*16,
                       s + (size_t)rg*DHEAD + kt + c*8);
            }
        };

        float acc[4][4][4];
#pragma unroll
        for (int i = 0; i < 4; i++)
#pragma unroll
            for (int j = 0; j < 4; j++)
#pragma unroll
                for (int f = 0; f < 4; f++) acc[i][j][f] = 0.f;

        load_stage(0, 0);
        cpa_commit();

        for (int it = 0; it < 4; ++it) {
            const int cur = it & 1;
            if (it + 1 < 4) { load_stage(cur ^ 1, (it + 1) << 5); cpa_commit(); cpa_wait<1>(); }
            else            { cpa_wait<0>(); }
            __syncthreads();

            const unsigned sb = sbase + cur*HSTAGE;
            const unsigned aA = sb + (wm*64 + rowA)*(LDK*2) + colA*2;
            const unsigned aB = sb + TILEB + (wn*32 + rowB)*(LDK*2) + colB*2;

#pragma unroll
            for (int ks = 0; ks < 2; ks++) {
                const unsigned ko = ks*32;
                unsigned bh[4][2];
#pragma unroll
                for (int p = 0; p < 2; p++) {
                    unsigned r0, r1, r2, r3;
                    ldm4(r0, r1, r2, r3, aB + p*16*(LDK*2) + ko);
                    bh[2*p][0]=r0; bh[2*p][1]=r1; bh[2*p+1][0]=r2; bh[2*p+1][1]=r3;
                }
#pragma unroll
                for (int mt = 0; mt < 4; mt++) {
                    unsigned a[4];
                    ldm4(a[0], a[1], a[2], a[3], aA + mt*16*(LDK*2) + ko);
#pragma unroll
                    for (int nt = 0; nt < 4; nt++)
                        mmah(acc[mt][nt], a[0],a[1],a[2],a[3], bh[nt][0], bh[nt][1]);
                }
            }
            __syncthreads();
        }

        // --- epilogue A: acc -> logits, per-warp 32-col row max ---
#pragma unroll
        for (int mt = 0; mt < 4; mt++) {
#pragma unroll
            for (int hh = 0; hh < 2; hh++) {
                const int ml = wm*64 + mt*16 + lr2 + hh*8;
                float mx = -3.4e38f;
#pragma unroll
                for (int nt = 0; nt < 4; nt++) {
                    const int nl = wn*32 + nt*8 + lc2;
                    const size_t off = (size_t)(m0 + ml)*SEQ + n0 + nl;
                    float2 am = *reinterpret_cast<const float2*>(&g_adjm[(size_t)h*SEQ*SEQ + off]);
                    float v0 = acc[mt][nt][hh*2+0] * SCALE + am.x;
                    float v1 = acc[mt][nt][hh*2+1] * SCALE + am.y;
                    acc[mt][nt][hh*2+0] = v0;
                    acc[mt][nt][hh*2+1] = v1;
                    mx = fmaxf(mx, fmaxf(v0, v1));
                }
                mx = fmaxf(mx, __shfl_xor_sync(0xffffffffu, mx, 1));
                mx = fmaxf(mx, __shfl_xor_sync(0xffffffffu, mx, 2));
                if (lc == 0) m_part[ml*4 + wn] = mx;
            }
        }
        __syncthreads();

        if (tid < 128) {
            float m4 = fmaxf(fmaxf(m_part[tid*4+0], m_part[tid*4+1]),
                             fmaxf(m_part[tid*4+2], m_part[tid*4+3]));
            tm[ntile*128 + tid] = m4;
        }
        __syncthreads();

        // --- epilogue B: u = exp(l - tile_max) -> g_uf fp16, per-warp partial sums ---
#pragma unroll
        for (int mt = 0; mt < 4; mt++) {
#pragma unroll
            for (int hh = 0; hh < 2; hh++) {
                const int ml = wm*64 + mt*16 + lr2 + hh*8;
                const float tmr = tm[ntile*128 + ml];
                float s = 0.f;
#pragma unroll
                for (int nt = 0; nt < 4; nt++) {
                    const int nl = wn*32 + nt*8 + lc2;
                    const size_t off = (size_t)(m0 + ml)*SEQ + n0 + nl;
                    float u0 = __expf(acc[mt][nt][hh*2+0] - tmr);
                    float u1 = __expf(acc[mt][nt][hh*2+1] - tmr);
                    *reinterpret_cast<unsigned*>(&ufz[off]) = packh(u0, u1);
                    s += u0 + u1;
                }
                s += __shfl_xor_sync(0xffffffffu, s, 1);
                s += __shfl_xor_sync(0xffffffffu, s, 2);
                if (lc == 0) s_part[ml*4 + wn] = s;
            }
        }
        __syncthreads();

        if (tid < 128)
            ts[ntile*128 + tid] = s_part[tid*4+0] + s_part[tid*4+1]
                                + s_part[tid*4+2] + s_part[tid*4+3];
        __syncthreads();
    }

    // ---- per-row global stats -> fac[t] = exp(tm[t]-m)/den ----
    if (tid < 128) {
        float mA = tm[tid], mB = tm[128 + tid], mC = tm[256 + tid], mD = tm[384 + tid];
        float m  = fmaxf(fmaxf(mA, mB), fmaxf(mC, mD));
        float eA = __expf(mA - m), eB = __expf(mB - m);
        float eC = __expf(mC - m), eD = __expf(mD - m);
        float den = ts[tid]*eA + ts[128+tid]*eB + ts[256+tid]*eC + ts[384+tid]*eD;
        float iden = 1.f / den;
        fac[tid]       = eA * iden;
        fac[128 + tid] = eB * iden;
        fac[256 + tid] = eC * iden;
        fac[384 + tid] = eD * iden;
    }
    __syncthreads();

    // ================= pass 2: P = u*fac, write fr, P @ V (fp16 single) =================
    const float* Bp = g_fv + (size_t)z*SEQ*DHEAD;
    const int arow  = tid >> 1;
    const int akoff = (tid & 1) << 3;
    const int bn    = tid & 127;
    const int bhalf = tid >> 7;

    uint4 ua;            // 8 halves of u
    float fb[8];
    auto ldg_stage = [&](int kt) {
        ua = *reinterpret_cast<const uint4*>(ufz + (size_t)(m0 + arow)*SEQ + kt + akoff);
#pragma unroll
        for (int j = 0; j < 8; j++)
            fb[j] = Bp[(size_t)(kt + 8*bhalf + j)*DHEAD + bn];
    };

    ldg_stage(0);

    float acc[4][4][4];
#pragma unroll
    for (int i = 0; i < 4; i++)
#pragma unroll
        for (int j = 0; j < 4; j++)
#pragma unroll
            for (int f = 0; f < 4; f++) acc[i][j][f] = 0.f;

    for (int it = 0; it < 32; ++it) {
        const unsigned b0 = (unsigned)(it & 1) * 3072;   // word stride per stage (12 KB)
        {
            const float fct = fac[(it >> 3)*128 + arow];   // ntile = it/8
            float2 u0 = h2f2(ua.x), u1 = h2f2(ua.y), u2 = h2f2(ua.z), u3 = h2f2(ua.w);
            float p0 = u0.x*fct, p1 = u0.y*fct, p2 = u1.x*fct, p3 = u1.y*fct;
            float p4 = u2.x*fct, p5 = u2.y*fct, p6 = u3.x*fct, p7 = u3.y*fct;

            float* ap = frz + (size_t)(m0 + arow)*SEQ + it*16 + akoff;
            *reinterpret_cast<float4*>(ap)     = make_float4(p0, p1, p2, p3);
            *reinterpret_cast<float4*>(ap + 4) = make_float4(p4, p5, p6, p7);

            uint4 pa = make_uint4(packh(p0, p1), packh(p2, p3),
                                  packh(p4, p5), packh(p6, p7));
            *reinterpret_cast<uint4*>(&pW[b0 + arow*12 + (akoff >> 1)]) = pa;
            uint4 pb = make_uint4(packh(fb[0], fb[1]), packh(fb[2], fb[3]),
                                  packh(fb[4], fb[5]), packh(fb[6], fb[7]));
            *reinterpret_cast<uint4*>(&pW[b0 + 1536 + bn*12 + 4*bhalf]) = pb;
        }
        __syncthreads();

        if (it + 1 < 32) ldg_stage((it + 1) * 16);

        uint2 a0[4], a1[4], b_h[4];
#pragma unroll
        for (int mt = 0; mt < 4; mt++) {
            const int r = wm*64 + mt*16 + lr2;
            a0[mt] = *reinterpret_cast<const uint2*>(&pW[b0 + r*12 + 2*lc]);
            a1[mt] = *reinterpret_cast<const uint2*>(&pW[b0 + (r+8)*12 + 2*lc]);
        }
#pragma unroll
        for (int nt = 0; nt < 4; nt++) {
            const int c = wn*32 + nt*8 + lr2;
            b_h[nt] = *reinterpret_cast<const uint2*>(&pW[b0 + 1536 + c*12 + 2*lc]);
        }
#pragma unroll
        for (int mt = 0; mt < 4; mt++)
#pragma unroll
            for (int nt = 0; nt < 4; nt++)
                mmah(acc[mt][nt], a0[mt].x, a1[mt].x, a0[mt].y, a1[mt].y, b_h[nt].x, b_h[nt].y);
    }

    // epilogue: emit attn fp16
    const int b = z >> 3;
#pragma unroll
    for (int mt = 0; mt < 4; mt++)
#pragma unroll
        for (int nt = 0; nt < 4; nt++) {
            const int mb = m0 + wm*64 + mt*16 + lr2;
            const int nb = wn*32 + nt*8 + lc2;
#pragma unroll
            for (int hh = 0; hh < 2; hh++) {
                const size_t idx = ((size_t)(b*SEQ + mb + hh*8))*DMODEL + h*DHEAD + nb;
                *reinterpret_cast<unsigned*>(&g_atf[idx]) =
                    packh(acc[mt][nt][hh*2+0], acc[mt][nt][hh*2+1]);
            }
        }
}

// ---------------- launch ----------------
extern "C" void kernel_launch(void* const* d_in, const int* in_sizes, int n_in,
                              void* d_out, int out_size)
{
    const float* x_q      = (const float*)d_in[0];
    const float* x_kv     = (const float*)d_in[1];
    const float* W_head_w = (const float*)d_in[2];
    const float* W_head_b = (const float*)d_in[3];
    const float* W_v_w    = (const float*)d_in[4];
    const float* W_v_b    = (const float*)d_in[5];
    const float* W_out_w  = (const float*)d_in[6];
    const float* W_out_b  = (const float*)d_in[7];
    const float* rel_emb  = (const float*)d_in[8];
    const float* col_head = (const float*)d_in[9];
    const float* col_tail = (const float*)d_in[10];

    float* out_x  = (float*)d_out;                          // [32,512,1024]
    float* out_fr = out_x + (size_t)BATCH*SEQ*DMODEL;       // [256,512,512]

    static bool attr_done = false;
    if (!attr_done) {
        cudaFuncSetAttribute(gemm_wide<0>, cudaFuncAttributeMaxDynamicSharedMemorySize, HG2_DSM);
        cudaFuncSetAttribute(gemm_wide<3>, cudaFuncAttributeMaxDynamicSharedMemorySize, HG2_DSM);
        cudaFuncSetAttribute(attn_fused,   cudaFuncAttributeMaxDynamicSharedMemorySize, FU_DSM);
        attr_done = true;
    }

    // 1) conversions (all fp16)
    cvt_x<<<dim3(2048, 2), 256>>>(x_q, x_kv);
    cvt_w<<<dim3(512, 3),  256>>>(W_head_w, W_v_w, W_out_w);

    // 2) learned column topology mask
    adj_kernel<<<dim3(SEQ, HEADS), 128>>>(col_head, col_tail);

    // 3) projections (fp16, 128x256 CTA tile, 64x64 warptiles, 3-stage pipeline)
    gemm_wide<0><<<dim3(4, 128, 3), 256, HG2_DSM>>>(W_head_b, W_v_b, rel_emb, nullptr, DMODEL);

    // 4) fused scores + softmax + P @ V -> fr final probs, attn fp16
    attn_fused<<<dim3(1, 4, BHS), 256, FU_DSM>>>(out_fr);

    // 5) output projection (same wide-tile core)
    gemm_wide<3><<<dim3(4, 128), 256, HG2_DSM>>>(W_out_b, nullptr, nullptr, out_x, DMODEL);
}

// round 17
// speedup vs baseline: 1.0840x; 1.0840x over previous
#include <cuda_runtime.h>
#include <cuda_bf16.h>
#include <cuda_fp16.h>
#include <math.h>
#include <cstdint>

#define BATCH   32
#define HEADS   8
#define SEQ     512
#define DMODEL  1024
#define DHEAD   128
#define DCOL    18
#define BHS     (BATCH*HEADS)   // 256
#define BSD     ((size_t)BATCH*SEQ*DMODEL)   // 16777216
#define SCALE   0.08838834764831845f

// ---------------- scratch (static device globals; no allocation) ----------------
__device__ __align__(256) __half        g_xqf[BSD], g_xkf[BSD];          // fp16 inputs
__device__ __align__(256) __half        g_Whf[DMODEL*DMODEL], g_Wvf[DMODEL*DMODEL];
__device__ __align__(256) __half        g_Wof[DMODEL*DMODEL];
__device__ __align__(256) __half        g_fhf[BSD], g_ftf[BSD];          // f_head/f_tail fp16
__device__ __align__(256) __half        g_fvf[BSD];                      // f_v fp16
__device__ __align__(256) __half        g_atf[BSD];                      // attn fp16
__device__ __align__(256) float         g_adjm[(size_t)HEADS*SEQ*SEQ];
__device__ __align__(256) __half        g_uf [(size_t)BHS*SEQ*SEQ];      // u = exp(l - tm) fp16

// ---------------- small helpers ----------------
__device__ __forceinline__ unsigned packh(float f0, float f1) {    // f0 -> low half
    unsigned d;
    asm("cvt.rn.f16x2.f32 %0, %1, %2;" : "=r"(d) : "f"(f1), "f"(f0));
    return d;
}
__device__ __forceinline__ float2 h2f2(unsigned p) {
    return __half22float2(*reinterpret_cast<__half2*>(&p));
}

__device__ __forceinline__ unsigned smem_u32(const void* p) {
    unsigned a;
    asm("{ .reg .u64 t; cvta.to.shared.u64 t, %1; cvt.u32.u64 %0, t; }" : "=r"(a) : "l"(p));
    return a;
}
__device__ __forceinline__ void cpa16s(unsigned dst, const void* src) {
    asm volatile("cp.async.ca.shared.global [%0], [%1], 16;" :: "r"(dst), "l"(src));
}
__device__ __forceinline__ void cpa_commit() { asm volatile("cp.async.commit_group;"); }
template<int N>
__device__ __forceinline__ void cpa_wait() { asm volatile("cp.async.wait_group %0;" :: "n"(N)); }

__device__ __forceinline__ void ldm4(unsigned& r0, unsigned& r1, unsigned& r2, unsigned& r3,
                                     unsigned addr) {
    asm volatile("ldmatrix.sync.aligned.m8n8.x4.shared.b16 {%0,%1,%2,%3}, [%4];"
                 : "=r"(r0), "=r"(r1), "=r"(r2), "=r"(r3) : "r"(addr));
}

__device__ __forceinline__ void mmah(float* c, unsigned a0, unsigned a1, unsigned a2,
                                     unsigned a3, unsigned b0, unsigned b1) {
    asm volatile(
        "mma.sync.aligned.m16n8k16.row.col.f32.f16.f16.f32 "
        "{%0,%1,%2,%3}, {%4,%5,%6,%7}, {%8,%9}, {%0,%1,%2,%3};\n"
        : "+f"(c[0]), "+f"(c[1]), "+f"(c[2]), "+f"(c[3])
        : "r"(a0), "r"(a1), "r"(a2), "r"(a3), "r"(b0), "r"(b1));
}

// ---------------- conversions (all fp16) ----------------
__global__ void cvt_x(const float* __restrict__ xq, const float* __restrict__ xkv)
{
    const int sel = blockIdx.y;
    const float4* s4 = reinterpret_cast<const float4*>(sel ? xkv : xq);
    uint2* out = reinterpret_cast<uint2*>(sel ? g_xkf : g_xqf);
    const int n4 = (int)(BSD/4);
    for (int i = blockIdx.x * blockDim.x + threadIdx.x; i < n4; i += gridDim.x * blockDim.x) {
        float4 v = s4[i];
        out[i] = make_uint2(packh(v.x, v.y), packh(v.z, v.w));
    }
}

__global__ void cvt_w(const float* __restrict__ wh, const float* __restrict__ wv,
                      const float* __restrict__ wo)
{
    const int sel = blockIdx.y;
    const float4* s4 = reinterpret_cast<const float4*>(sel == 0 ? wh : sel == 1 ? wv : wo);
    uint2* out = reinterpret_cast<uint2*>(sel == 0 ? g_Whf : sel == 1 ? g_Wvf : g_Wof);
    const int n4 = DMODEL*DMODEL/4;
    for (int i = blockIdx.x * blockDim.x + threadIdx.x; i < n4; i += gridDim.x * blockDim.x) {
        float4 v = s4[i];
        out[i] = make_uint2(packh(v.x, v.y), packh(v.z, v.w));
    }
}

// ---------------- adjacency: softmax(col_head @ col_tail^T, diag=0) ----------------
__global__ void adj_kernel(const float* __restrict__ col_head,
                           const float* __restrict__ col_tail)
{
    const int q = blockIdx.x;
    const int h = blockIdx.y;
    const int t = threadIdx.x;                 // 128 threads
    __shared__ float ch[DCOL];
    __shared__ float sred[4];

    if (t < DCOL) ch[t] = col_head[((size_t)h*SEQ + q)*DCOL + t];
    __syncthreads();

    float l[4];
#pragma unroll
    for (int i = 0; i < 4; i++) {
        const int k = t + i*128;
        const float* ct = col_tail + ((size_t)h*SEQ + k)*DCOL;
        float s = 0.f;
#pragma unroll
        for (int c = 0; c < DCOL; c++) s += ch[c]*ct[c];
        l[i] = (k == q) ? 0.f : s;
    }

    float mx = fmaxf(fmaxf(l[0],l[1]), fmaxf(l[2],l[3]));
#pragma unroll
    for (int o = 16; o; o >>= 1) mx = fmaxf(mx, __shfl_xor_sync(0xffffffffu, mx, o));
    if ((t & 31) == 0) sred[t >> 5] = mx;
    __syncthreads();
    mx = fmaxf(fmaxf(sred[0],sred[1]), fmaxf(sred[2],sred[3]));
    __syncthreads();

    float e[4]; float sum = 0.f;
#pragma unroll
    for (int i = 0; i < 4; i++) { e[i] = expf(l[i]-mx); sum += e[i]; }
#pragma unroll
    for (int o = 16; o; o >>= 1) sum += __shfl_xor_sync(0xffffffffu, sum, o);
    if ((t & 31) == 0) sred[t >> 5] = sum;
    __syncthreads();
    sum = sred[0]+sred[1]+sred[2]+sred[3];
    const float inv = 1.f/sum;

    float* dst = g_adjm + ((size_t)h*SEQ + q)*SEQ;
#pragma unroll
    for (int i = 0; i < 4; i++) {
        const int k = t + i*128;
        dst[k] = (1.f - e[i]*inv) * (-10000.f);
    }
}

// ---------------- tile constants ----------------
#define LDK     40                  // padded smem row (16b elems), 80 B
#define TILEB   (128*LDK*2)         // 10240 B
#define HSTAGE  (2*TILEB)           // fp16 single: A + B
#define HG_DSM  (3*HSTAGE)          // 61440 (3-stage)

// ---------------- fp16 single-pass projections: blockIdx.z = mode (0,1,2) ----------------
__global__ void __launch_bounds__(256, 2)
proj_h(const float* __restrict__ biasH, const float* __restrict__ biasV,
       const float* __restrict__ aux, int K)
{
    extern __shared__ char sm[];
    const unsigned sbase = smem_u32(sm);

    const int tid  = threadIdx.x;
    const int lane = tid & 31;
    const int warp = tid >> 5;
    const int wm   = warp >> 2, wn = warp & 3;
    const int mode = blockIdx.z;
    const int m0   = blockIdx.y * 128;
    const int n0   = blockIdx.x * 128;

    const __half* A = (mode == 0) ? g_xqf : g_xkf;
    const __half* B = (mode == 2) ? g_Wvf : g_Whf;
    const float* bias = (mode == 2) ? biasV : biasH;

    auto load_stage = [&](int st, int kt) {
        const unsigned sb = sbase + st*HSTAGE;
#pragma unroll
        for (int i = 0; i < 4; i++) {
            const int idx  = tid + i*256;
            const int tile = idx >> 9;
            const int r    = (idx >> 2) & 127;
            const int c    = idx & 3;
            const __half* s = tile ? B : A;
            const int rg = (tile ? n0 : m0) + r;
            cpa16s(sb + tile*TILEB + r*(LDK*2) + c*16,
                   s + (size_t)rg*K + kt + c*8);
        }
    };

    float acc[4][4][4];
#pragma unroll
    for (int i = 0; i < 4; i++)
#pragma unroll
        for (int j = 0; j < 4; j++)
#pragma unroll
            for (int f = 0; f < 4; f++) acc[i][j][f] = 0.f;

    const int rowA = (lane & 7) + ((lane >> 3) & 1) * 8;
    const int colA = ((lane >> 4) & 1) * 8;
    const int rowB = (lane & 7) + ((lane >> 4) & 1) * 8;
    const int colB = ((lane >> 3) & 1) * 8;

    const int iters = K >> 5;
    load_stage(0, 0);  cpa_commit();
    load_stage(1, 32); cpa_commit();

    int cur = 0;
    for (int it = 0; it < iters; ++it) {
        if (it + 1 < iters) cpa_wait<1>();
        else                cpa_wait<0>();
        __syncthreads();
        if (it + 2 < iters) {
            load_stage((cur + 2) % 3, (it + 2) << 5);
            cpa_commit();
        }

        const unsigned sb = sbase + cur*HSTAGE;
        const unsigned aA = sb + (wm*64 + rowA)*(LDK*2) + colA*2;
        const unsigned aB = sb + TILEB + (wn*32 + rowB)*(LDK*2) + colB*2;

#pragma unroll
        for (int ks = 0; ks < 2; ks++) {
            const unsigned ko = ks*32;
            unsigned bh[4][2];
#pragma unroll
            for (int p = 0; p < 2; p++) {
                unsigned r0, r1, r2, r3;
                ldm4(r0, r1, r2, r3, aB + p*16*(LDK*2) + ko);
                bh[2*p][0]=r0; bh[2*p][1]=r1; bh[2*p+1][0]=r2; bh[2*p+1][1]=r3;
            }
#pragma unroll
            for (int mt = 0; mt < 4; mt++) {
                unsigned a[4];
                ldm4(a[0], a[1], a[2], a[3], aA + mt*16*(LDK*2) + ko);
#pragma unroll
                for (int nt = 0; nt < 4; nt++)
                    mmah(acc[mt][nt], a[0],a[1],a[2],a[3], bh[nt][0], bh[nt][1]);
            }
        }
        cur = (cur == 2) ? 0 : cur + 1;
    }

    const int lr2 = lane >> 2;
    const int lc2 = (lane & 3) << 1;
#pragma unroll
    for (int mt = 0; mt < 4; mt++)
#pragma unroll
        for (int nt = 0; nt < 4; nt++) {
#pragma unroll
            for (int hh = 0; hh < 2; hh++) {
                const int m = m0 + wm*64 + mt*16 + lr2 + hh*8;
                const int n = n0 + wn*32 + nt*8 + lc2;
                float v0 = acc[mt][nt][hh*2+0] + bias[n];
                float v1 = acc[mt][nt][hh*2+1] + bias[n+1];
                const int b = m >> 9, q = m & 511, h = n >> 7, dh = n & 127;
                const size_t idx = (((size_t)((b<<3)|h))*SEQ + q)*DHEAD + dh;
                if (mode < 2) {
                    v0 *= aux[n]; v1 *= aux[n+1];
                    __half* dst = (mode == 0) ? g_fhf : g_ftf;
                    *reinterpret_cast<unsigned*>(&dst[idx]) = packh(v0, v1);
                } else {
                    *reinterpret_cast<unsigned*>(&g_fvf[idx]) = packh(v0, v1);
                }
            }
        }
}

// ---------------- fused scores + softmax + P @ V ----------------
// pass 1 writes u = exp(l - tile_max) as fp16 -> g_uf, per-tile (max, sum).
// pass 2: P = u * fac, writes fr (only fp32 write), P @ V fp16 (V fp16 direct).
#define FU_TM    49152                 // tm:  [4][128] fp32 (2 KB)
#define FU_TS    (FU_TM + 2048)        // ts:  [4][128]
#define FU_MP    (FU_TM + 4096)        // m_part: [128][4]
#define FU_SP    (FU_TM + 6144)        // s_part: [128][4]
#define FU_FAC   (FU_TM + 8192)        // fac: [4][128]
#define FU_DSM   (FU_TM + 10240)       // 59392

__global__ void __launch_bounds__(256, 2)
attn_fused(float* __restrict__ fr)
{
    extern __shared__ char sm[];
    const unsigned sbase = smem_u32(sm);
    unsigned* pW  = reinterpret_cast<unsigned*>(sm);
    float* tm     = reinterpret_cast<float*>(sm + FU_TM);
    float* ts     = reinterpret_cast<float*>(sm + FU_TS);
    float* m_part = reinterpret_cast<float*>(sm + FU_MP);
    float* s_part = reinterpret_cast<float*>(sm + FU_SP);
    float* fac    = reinterpret_cast<float*>(sm + FU_FAC);

    const int tid  = threadIdx.x;
    const int lane = tid & 31;
    const int warp = tid >> 5;
    const int wm   = warp >> 2, wn = warp & 3;
    const int lr2  = lane >> 2;
    const int lc2  = (lane & 3) << 1;
    const int lc   = lane & 3;
    const int z    = blockIdx.z;
    const int m0   = blockIdx.y * 128;
    const int h    = z & 7;

    const __half* Af = g_fhf + (size_t)z*SEQ*DHEAD;
    const __half* Bf = g_ftf + (size_t)z*SEQ*DHEAD;
    float*  frz = fr   + (size_t)z*SEQ*SEQ;
    __half* ufz = g_uf + (size_t)z*SEQ*SEQ;

    const int rowA = (lane & 7) + ((lane >> 3) & 1) * 8;
    const int colA = ((lane >> 4) & 1) * 8;
    const int rowB = (lane & 7) + ((lane >> 4) & 1) * 8;
    const int colB = ((lane >> 3) & 1) * 8;

    // ================= pass 1: scores -> u fp16, per-tile stats =================
    for (int ntile = 0; ntile < 4; ++ntile) {
        const int n0 = ntile * 128;

        auto load_stage = [&](int st, int kt) {
            const unsigned sb = sbase + st*HSTAGE;
#pragma unroll
            for (int i = 0; i < 4; i++) {
                const int idx  = tid + i*256;
                const int tile = idx >> 9;
                const int r    = (idx >> 2) & 127;
                const int c    = idx & 3;
                const __half* s = tile ? Bf : Af;
                const int rg = (tile ? n0 : m0) + r;
                cpa16s(sb + tile*TILEB + r*(LDK*2) + c*16,
                       s + (size_t)rg*DHEAD + kt + c*8);
            }
        };

        float acc[4][4][4];
#pragma unroll
        for (int i = 0; i < 4; i++)
#pragma unroll
            for (int j = 0; j < 4; j++)
#pragma unroll
                for (int f = 0; f < 4; f++) acc[i][j][f] = 0.f;

        load_stage(0, 0);
        cpa_commit();

        for (int it = 0; it < 4; ++it) {
            const int cur = it & 1;
            if (it + 1 < 4) { load_stage(cur ^ 1, (it + 1) << 5); cpa_commit(); cpa_wait<1>(); }
            else            { cpa_wait<0>(); }
            __syncthreads();

            const unsigned sb = sbase + cur*HSTAGE;
            const unsigned aA = sb + (wm*64 + rowA)*(LDK*2) + colA*2;
            const unsigned aB = sb + TILEB + (wn*32 + rowB)*(LDK*2) + colB*2;

#pragma unroll
            for (int ks = 0; ks < 2; ks++) {
                const unsigned ko = ks*32;
                unsigned bh[4][2];
#pragma unroll
                for (int p = 0; p < 2; p++) {
                    unsigned r0, r1, r2, r3;
                    ldm4(r0, r1, r2, r3, aB + p*16*(LDK*2) + ko);
                    bh[2*p][0]=r0; bh[2*p][1]=r1; bh[2*p+1][0]=r2; bh[2*p+1][1]=r3;
                }
#pragma unroll
                for (int mt = 0; mt < 4; mt++) {
                    unsigned a[4];
                    ldm4(a[0], a[1], a[2], a[3], aA + mt*16*(LDK*2) + ko);
#pragma unroll
                    for (int nt = 0; nt < 4; nt++)
                        mmah(acc[mt][nt], a[0],a[1],a[2],a[3], bh[nt][0], bh[nt][1]);
                }
            }
            __syncthreads();
        }

        // --- epilogue A: acc -> logits, per-warp 32-col row max ---
#pragma unroll
        for (int mt = 0; mt < 4; mt++) {
#pragma unroll
            for (int hh = 0; hh < 2; hh++) {
                const int ml = wm*64 + mt*16 + lr2 + hh*8;
                float mx = -3.4e38f;
#pragma unroll
                for (int nt = 0; nt < 4; nt++) {
                    const int nl = wn*32 + nt*8 + lc2;
                    const size_t off = (size_t)(m0 + ml)*SEQ + n0 + nl;
                    float2 am = *reinterpret_cast<const float2*>(&g_adjm[(size_t)h*SEQ*SEQ + off]);
                    float v0 = acc[mt][nt][hh*2+0] * SCALE + am.x;
                    float v1 = acc[mt][nt][hh*2+1] * SCALE + am.y;
                    acc[mt][nt][hh*2+0] = v0;
                    acc[mt][nt][hh*2+1] = v1;
                    mx = fmaxf(mx, fmaxf(v0, v1));
                }
                mx = fmaxf(mx, __shfl_xor_sync(0xffffffffu, mx, 1));
                mx = fmaxf(mx, __shfl_xor_sync(0xffffffffu, mx, 2));
                if (lc == 0) m_part[ml*4 + wn] = mx;
            }
        }
        __syncthreads();

        if (tid < 128) {
            float m4 = fmaxf(fmaxf(m_part[tid*4+0], m_part[tid*4+1]),
                             fmaxf(m_part[tid*4+2], m_part[tid*4+3]));
            tm[ntile*128 + tid] = m4;
        }
        __syncthreads();

        // --- epilogue B: u = exp(l - tile_max) -> g_uf fp16, per-warp partial sums ---
#pragma unroll
        for (int mt = 0; mt < 4; mt++) {
#pragma unroll
            for (int hh = 0; hh < 2; hh++) {
                const int ml = wm*64 + mt*16 + lr2 + hh*8;
                const float tmr = tm[ntile*128 + ml];
                float s = 0.f;
#pragma unroll
                for (int nt = 0; nt < 4; nt++) {
                    const int nl = wn*32 + nt*8 + lc2;
                    const size_t off = (size_t)(m0 + ml)*SEQ + n0 + nl;
                    float u0 = __expf(acc[mt][nt][hh*2+0] - tmr);
                    float u1 = __expf(acc[mt][nt][hh*2+1] - tmr);
                    *reinterpret_cast<unsigned*>(&ufz[off]) = packh(u0, u1);
                    s += u0 + u1;
                }
                s += __shfl_xor_sync(0xffffffffu, s, 1);
                s += __shfl_xor_sync(0xffffffffu, s, 2);
                if (lc == 0) s_part[ml*4 + wn] = s;
            }
        }
        __syncthreads();

        if (tid < 128)
            ts[ntile*128 + tid] = s_part[tid*4+0] + s_part[tid*4+1]
                                + s_part[tid*4+2] + s_part[tid*4+3];
        __syncthreads();
    }

    // ---- per-row global stats -> fac[t] = exp(tm[t]-m)/den ----
    if (tid < 128) {
        float mA = tm[tid], mB = tm[128 + tid], mC = tm[256 + tid], mD = tm[384 + tid];
        float m  = fmaxf(fmaxf(mA, mB), fmaxf(mC, mD));
        float eA = __expf(mA - m), eB = __expf(mB - m);
        float eC = __expf(mC - m), eD = __expf(mD - m);
        float den = ts[tid]*eA + ts[128+tid]*eB + ts[256+tid]*eC + ts[384+tid]*eD;
        float iden = 1.f / den;
        fac[tid]       = eA * iden;
        fac[128 + tid] = eB * iden;
        fac[256 + tid] = eC * iden;
        fac[384 + tid] = eD * iden;
    }
    __syncthreads();

    // ================= pass 2: P = u*fac, write fr, P @ V (fp16 single) =================
    const __half* Bp = g_fvf + (size_t)z*SEQ*DHEAD;
    const int arow  = tid >> 1;
    const int akoff = (tid & 1) << 3;
    const int bn    = tid & 127;
    const int bhalf = tid >> 7;

    uint4 ua;                 // 8 halves of u
    unsigned short vb[8];     // 8 halves of V (column bn, 8 k-rows)
    auto ldg_stage = [&](int kt) {
        ua = *reinterpret_cast<const uint4*>(ufz + (size_t)(m0 + arow)*SEQ + kt + akoff);
#pragma unroll
        for (int j = 0; j < 8; j++)
            vb[j] = *reinterpret_cast<const unsigned short*>(
                        &Bp[(size_t)(kt + 8*bhalf + j)*DHEAD + bn]);
    };

    ldg_stage(0);

    float acc[4][4][4];
#pragma unroll
    for (int i = 0; i < 4; i++)
#pragma unroll
        for (int j = 0; j < 4; j++)
#pragma unroll
            for (int f = 0; f < 4; f++) acc[i][j][f] = 0.f;

    for (int it = 0; it < 32; ++it) {
        const unsigned b0 = (unsigned)(it & 1) * 3072;   // word stride per stage (12 KB)
        {
            const float fct = fac[(it >> 3)*128 + arow];   // ntile = it/8
            float2 u0 = h2f2(ua.x), u1 = h2f2(ua.y), u2 = h2f2(ua.z), u3 = h2f2(ua.w);
            float p0 = u0.x*fct, p1 = u0.y*fct, p2 = u1.x*fct, p3 = u1.y*fct;
            float p4 = u2.x*fct, p5 = u2.y*fct, p6 = u3.x*fct, p7 = u3.y*fct;

            float* ap = frz + (size_t)(m0 + arow)*SEQ + it*16 + akoff;
            *reinterpret_cast<float4*>(ap)     = make_float4(p0, p1, p2, p3);
            *reinterpret_cast<float4*>(ap + 4) = make_float4(p4, p5, p6, p7);

            uint4 pa = make_uint4(packh(p0, p1), packh(p2, p3),
                                  packh(p4, p5), packh(p6, p7));
            *reinterpret_cast<uint4*>(&pW[b0 + arow*12 + (akoff >> 1)]) = pa;
            // V already fp16: pure bit packing, no conversion
            uint4 pb = make_uint4((unsigned)vb[0] | ((unsigned)vb[1] << 16),
                                  (unsigned)vb[2] | ((unsigned)vb[3] << 16),
                                  (unsigned)vb[4] | ((unsigned)vb[5] << 16),
                                  (unsigned)vb[6] | ((unsigned)vb[7] << 16));
            *reinterpret_cast<uint4*>(&pW[b0 + 1536 + bn*12 + 4*bhalf]) = pb;
        }
        __syncthreads();

        if (it + 1 < 32) ldg_stage((it + 1) * 16);

        uint2 a0[4], a1[4], b_h[4];
#pragma unroll
        for (int mt = 0; mt < 4; mt++) {
            const int r = wm*64 + mt*16 + lr2;
            a0[mt] = *reinterpret_cast<const uint2*>(&pW[b0 + r*12 + 2*lc]);
            a1[mt] = *reinterpret_cast<const uint2*>(&pW[b0 + (r+8)*12 + 2*lc]);
        }
#pragma unroll
        for (int nt = 0; nt < 4; nt++) {
            const int c = wn*32 + nt*8 + lr2;
            b_h[nt] = *reinterpret_cast<const uint2*>(&pW[b0 + 1536 + c*12 + 2*lc]);
        }
#pragma unroll
        for (int mt = 0; mt < 4; mt++)
#pragma unroll
            for (int nt = 0; nt < 4; nt++)
                mmah(acc[mt][nt], a0[mt].x, a1[mt].x, a0[mt].y, a1[mt].y, b_h[nt].x, b_h[nt].y);
    }

    // epilogue: emit attn fp16
    const int b = z >> 3;
#pragma unroll
    for (int mt = 0; mt < 4; mt++)
#pragma unroll
        for (int nt = 0; nt < 4; nt++) {
            const int mb = m0 + wm*64 + mt*16 + lr2;
            const int nb = wn*32 + nt*8 + lc2;
#pragma unroll
            for (int hh = 0; hh < 2; hh++) {
                const size_t idx = ((size_t)(b*SEQ + mb + hh*8))*DMODEL + h*DHEAD + nb;
                *reinterpret_cast<unsigned*>(&g_atf[idx]) =
                    packh(acc[mt][nt][hh*2+0], acc[mt][nt][hh*2+1]);
            }
        }
}

// ---------------- output projection (fp16 single-pass, 3-stage) ----------------
__global__ void __launch_bounds__(256, 2)
out_h(const float* __restrict__ bias, float* __restrict__ Cext, int K)
{
    extern __shared__ char sm[];
    const unsigned sbase = smem_u32(sm);

    const int tid  = threadIdx.x;
    const int lane = tid & 31;
    const int warp = tid >> 5;
    const int wm   = warp >> 2, wn = warp & 3;
    const int m0   = blockIdx.y * 128;
    const int n0   = blockIdx.x * 128;

    const __half* A = g_atf;
    const __half* B = g_Wof;

    auto load_stage = [&](int st, int kt) {
        const unsigned sb = sbase + st*HSTAGE;
#pragma unroll
        for (int i = 0; i < 4; i++) {
            const int idx  = tid + i*256;
            const int tile = idx >> 9;
            const int r    = (idx >> 2) & 127;
            const int c    = idx & 3;
            const __half* s = tile ? B : A;
            const int rg = (tile ? n0 : m0) + r;
            cpa16s(sb + tile*TILEB + r*(LDK*2) + c*16,
                   s + (size_t)rg*K + kt + c*8);
        }
    };

    float acc[4][4][4];
#pragma unroll
    for (int i = 0; i < 4; i++)
#pragma unroll
        for (int j = 0; j < 4; j++)
#pragma unroll
            for (int f = 0; f < 4; f++) acc[i][j][f] = 0.f;

    const int rowA = (lane & 7) + ((lane >> 3) & 1) * 8;
    const int colA = ((lane >> 4) & 1) * 8;
    const int rowB = (lane & 7) + ((lane >> 4) & 1) * 8;
    const int colB = ((lane >> 3) & 1) * 8;

    const int iters = K >> 5;
    load_stage(0, 0);  cpa_commit();
    load_stage(1, 32); cpa_commit();

    int cur = 0;
    for (int it = 0; it < iters; ++it) {
        if (it + 1 < iters) cpa_wait<1>();
        else                cpa_wait<0>();
        __syncthreads();
        if (it + 2 < iters) {
            load_stage((cur + 2) % 3, (it + 2) << 5);
            cpa_commit();
        }

        const unsigned sb = sbase + cur*HSTAGE;
        const unsigned aA = sb + (wm*64 + rowA)*(LDK*2) + colA*2;
        const unsigned aB = sb + TILEB + (wn*32 + rowB)*(LDK*2) + colB*2;

#pragma unroll
        for (int ks = 0; ks < 2; ks++) {
            const unsigned ko = ks*32;
            unsigned bh[4][2];
#pragma unroll
            for (int p = 0; p < 2; p++) {
                unsigned r0, r1, r2, r3;
                ldm4(r0, r1, r2, r3, aB + p*16*(LDK*2) + ko);
                bh[2*p][0]=r0; bh[2*p][1]=r1; bh[2*p+1][0]=r2; bh[2*p+1][1]=r3;
            }
#pragma unroll
            for (int mt = 0; mt < 4; mt++) {
                unsigned a[4];
                ldm4(a[0], a[1], a[2], a[3], aA + mt*16*(LDK*2) + ko);
#pragma unroll
                for (int nt = 0; nt < 4; nt++)
                    mmah(acc[mt][nt], a[0],a[1],a[2],a[3], bh[nt][0], bh[nt][1]);
            }
        }
        cur = (cur == 2) ? 0 : cur + 1;
    }

    const int lr2 = lane >> 2;
    const int lc2 = (lane & 3) << 1;
#pragma unroll
    for (int mt = 0; mt < 4; mt++)
#pragma unroll
        for (int nt = 0; nt < 4; nt++) {
#pragma unroll
            for (int hh = 0; hh < 2; hh++) {
                const int m = m0 + wm*64 + mt*16 + lr2 + hh*8;
                const int n = n0 + wn*32 + nt*8 + lc2;
                float2 o;
                o.x = acc[mt][nt][hh*2+0] + bias[n];
                o.y = acc[mt][nt][hh*2+1] + bias[n+1];
                *reinterpret_cast<float2*>(&Cext[(size_t)m*DMODEL + n]) = o;
            }
        }
}

// ---------------- launch ----------------
extern "C" void kernel_launch(void* const* d_in, const int* in_sizes, int n_in,
                              void* d_out, int out_size)
{
    const float* x_q      = (const float*)d_in[0];
    const float* x_kv     = (const float*)d_in[1];
    const float* W_head_w = (const float*)d_in[2];
    const float* W_head_b = (const float*)d_in[3];
    const float* W_v_w    = (const float*)d_in[4];
    const float* W_v_b    = (const float*)d_in[5];
    const float* W_out_w  = (const float*)d_in[6];
    const float* W_out_b  = (const float*)d_in[7];
    const float* rel_emb  = (const float*)d_in[8];
    const float* col_head = (const float*)d_in[9];
    const float* col_tail = (const float*)d_in[10];

    float* out_x  = (float*)d_out;                          // [32,512,1024]
    float* out_fr = out_x + (size_t)BATCH*SEQ*DMODEL;       // [256,512,512]

    static bool attr_done = false;
    if (!attr_done) {
        cudaFuncSetAttribute(proj_h,     cudaFuncAttributeMaxDynamicSharedMemorySize, HG_DSM);
        cudaFuncSetAttribute(attn_fused, cudaFuncAttributeMaxDynamicSharedMemorySize, FU_DSM);
        cudaFuncSetAttribute(out_h,      cudaFuncAttributeMaxDynamicSharedMemorySize, HG_DSM);
        attr_done = true;
    }

    // 1) conversions (all fp16)
    cvt_x<<<dim3(2048, 2), 256>>>(x_q, x_kv);
    cvt_w<<<dim3(512, 3),  256>>>(W_head_w, W_v_w, W_out_w);

    // 2) learned column topology mask
    adj_kernel<<<dim3(SEQ, HEADS), 128>>>(col_head, col_tail);

    // 3) projections (fp16 single-pass, merged, 3-stage pipeline)
    proj_h<<<dim3(8, 128, 3), 256, HG_DSM>>>(W_head_b, W_v_b, rel_emb, DMODEL);

    // 4) fused scores + softmax + P @ V -> fr final probs, attn fp16
    attn_fused<<<dim3(1, 4, BHS), 256, FU_DSM>>>(out_fr);

    // 5) output projection (fp16 single-pass, 3-stage pipeline)
    out_h<<<dim3(8, 128), 256, HG_DSM>>>(W_out_b, out_x, DMODEL);
}